// round 7
// baseline (speedup 1.0000x reference)
#include <cuda_runtime.h>
#include <cstdint>

#define NHEAD 12
#define HD 64
#define NTOK 512
#define NBATCH 32
#define DIM 768
#define MTOK (NBATCH*NTOK)
#define QKV_N (3*DIM)
#define ATTN_SCALE 0.125f

__device__ float g_q[(size_t)NBATCH*NHEAD*NTOK*HD];
__device__ float g_k[(size_t)NBATCH*NHEAD*NTOK*HD];
__device__ float g_v[(size_t)NBATCH*NHEAD*NTOK*HD];
__device__ float g_biasp[(size_t)NHEAD*NTOK*NTOK];   // c-frag layout [h][rt][ch][nt][lane][reg]
__device__ float g_attnout[(size_t)MTOK*DIM];

__device__ __forceinline__ uint32_t f2tf32(float x){
    uint32_t r; asm("cvt.rna.tf32.f32 %0, %1;" : "=r"(r) : "f"(x)); return r;
}
__device__ __forceinline__ void mma_tf32(float* c,const uint32_t* a,const uint32_t* b){
    asm volatile("mma.sync.aligned.m16n8k8.row.col.f32.tf32.tf32.f32 "
        "{%0,%1,%2,%3}, {%4,%5,%6,%7}, {%8,%9}, {%0,%1,%2,%3};"
        : "+f"(c[0]),"+f"(c[1]),"+f"(c[2]),"+f"(c[3])
        : "r"(a[0]),"r"(a[1]),"r"(a[2]),"r"(a[3]),"r"(b[0]),"r"(b[1]));
}

// ---- bias gather into c-fragment layout ----
__global__ void bias_gather_kernel(const float* __restrict__ table,
                                   const int* __restrict__ idx)
{
    int e = blockIdx.x*256 + threadIdx.x;       // 0..262143
    int rt=e>>13, kt=(e>>10)&7, nt=(e>>7)&7, lane=(e>>2)&31, reg=e&3;
    int g=lane>>2, l=lane&3;
    int row = rt*16 + g + 8*(reg>>1);
    int col = kt*64 + nt*8 + 2*l + (reg&1);
    int id = idx[row*NTOK + col];
    const float* t = table + (size_t)id*NHEAD;
#pragma unroll
    for (int h=0; h<NHEAD; h++)
        g_biasp[(size_t)h*262144 + e] = t[h];
}

// ---- TF32 GEMM, double-buffered, pair-packed B frags ----
// B layout: Bs[((np*4+ks)*32 + 4*g + (l^sgB))*4 + 2*ntl + kh], sgB=((ks^np)&3)^(g>>1)
template<int MODE>
__global__ __launch_bounds__(256,2)
void gemm_tf32_kernel(const float* __restrict__ Ain,const float* __restrict__ Bw,
                      const float* __restrict__ biasv,float* __restrict__ Cout,
                      int M,int Nn,int K)
{
    __shared__ uint32_t As[2][4096];
    __shared__ uint32_t Bs[2][4096];
    const float* A = (MODE==0) ? g_attnout : Ain;
    const int tid=threadIdx.x, warp=tid>>5, lane=tid&31;
    const int wm=warp&3, wn=warp>>2;
    const int m0=blockIdx.y*128, n0=blockIdx.x*128;
    const int nT = K >> 5;

    // hoisted fill STS offsets + swizzle groups
    int aoff[4], boff[4], sgA[4], sgB[4];
#pragma unroll
    for (int u=0; u<4; u++) {
        int f4=tid+256*u, row=f4>>3, kq=f4&7, ks=kq>>1, kh=kq&1, g=row&7;
        int mt=row>>4, r8=(row>>3)&1;
        sgA[u]=(ks^(g>>1))&3;
        aoff[u]=((mt*4+ks)*32+4*g)*4 + r8 + 2*kh;
        int nt=row>>3, np=nt>>1, ntl=nt&1;
        sgB[u]=(((ks^np)&3)^(g>>1))&3;
        boff[u]=((np*4+ks)*32+4*g)*4 + 2*ntl + kh;
    }

    float acc[2][8][4];
#pragma unroll
    for(int i=0;i<2;i++)
#pragma unroll
        for(int j=0;j<8;j++)
#pragma unroll
            for(int r=0;r<4;r++) acc[i][j][r]=0.f;

    float4 av[4], bv[4];
#pragma unroll
    for (int u=0; u<4; u++) {
        int f4=tid+256*u, row=f4>>3, kq=f4&7;
        av[u] = *(const float4*)&A [(size_t)(m0+row)*K + kq*4];
        bv[u] = *(const float4*)&Bw[(size_t)(n0+row)*K + kq*4];
    }
#pragma unroll
    for (int u=0; u<4; u++) {
        As[0][aoff[u]+((0^sgA[u])<<2)]=f2tf32(av[u].x);
        As[0][aoff[u]+((1^sgA[u])<<2)]=f2tf32(av[u].y);
        As[0][aoff[u]+((2^sgA[u])<<2)]=f2tf32(av[u].z);
        As[0][aoff[u]+((3^sgA[u])<<2)]=f2tf32(av[u].w);
        Bs[0][boff[u]+((0^sgB[u])<<2)]=f2tf32(bv[u].x);
        Bs[0][boff[u]+((1^sgB[u])<<2)]=f2tf32(bv[u].y);
        Bs[0][boff[u]+((2^sgB[u])<<2)]=f2tf32(bv[u].z);
        Bs[0][boff[u]+((3^sgB[u])<<2)]=f2tf32(bv[u].w);
    }
    __syncthreads();

    for (int t=0; t<nT; t++) {
        const int cur = t&1, nxt = cur^1;
        const bool hasNext = (t+1 < nT);
        if (hasNext) {
            int kt=(t+1)<<5;
#pragma unroll
            for (int u=0; u<4; u++) {
                int f4=tid+256*u, row=f4>>3, kq=f4&7;
                av[u] = *(const float4*)&A [(size_t)(m0+row)*K + kt + kq*4];
                bv[u] = *(const float4*)&Bw[(size_t)(n0+row)*K + kt + kq*4];
            }
        }
#pragma unroll
        for (int ks=0; ks<4; ks++) {
            int sa = lane ^ ((ks^(lane>>3))&3);
            uint32_t afr[2][4];
#pragma unroll
            for (int mt2=0; mt2<2; mt2++) {
                int mt=wm*2+mt2;
                *(uint4*)afr[mt2] = *(const uint4*)&As[cur][((mt*4+ks)*32+sa)*4];
            }
#pragma unroll
            for (int np2=0; np2<4; np2++) {
                int np = wn*4 + np2;
                int sb = lane ^ ((((ks^np)&3)^(lane>>3))&3);
                uint4 bq = *(const uint4*)&Bs[cur][((np*4+ks)*32+sb)*4];
                mma_tf32(acc[0][2*np2+0],afr[0],&bq.x);
                mma_tf32(acc[1][2*np2+0],afr[1],&bq.x);
                mma_tf32(acc[0][2*np2+1],afr[0],&bq.z);
                mma_tf32(acc[1][2*np2+1],afr[1],&bq.z);
            }
        }
        if (hasNext) {
#pragma unroll
            for (int u=0; u<4; u++) {
                As[nxt][aoff[u]+((0^sgA[u])<<2)]=f2tf32(av[u].x);
                As[nxt][aoff[u]+((1^sgA[u])<<2)]=f2tf32(av[u].y);
                As[nxt][aoff[u]+((2^sgA[u])<<2)]=f2tf32(av[u].z);
                As[nxt][aoff[u]+((3^sgA[u])<<2)]=f2tf32(av[u].w);
                Bs[nxt][boff[u]+((0^sgB[u])<<2)]=f2tf32(bv[u].x);
                Bs[nxt][boff[u]+((1^sgB[u])<<2)]=f2tf32(bv[u].y);
                Bs[nxt][boff[u]+((2^sgB[u])<<2)]=f2tf32(bv[u].z);
                Bs[nxt][boff[u]+((3^sgB[u])<<2)]=f2tf32(bv[u].w);
            }
        }
        __syncthreads();
    }

    const int gr=lane>>2, gl=lane&3;
#pragma unroll
    for (int mt2=0; mt2<2; mt2++) {
#pragma unroll
        for (int nt2=0; nt2<8; nt2++) {
            int n = n0 + wn*64 + nt2*8 + gl*2;
            float b0=biasv[n], b1=biasv[n+1];
#pragma unroll
            for (int half=0; half<2; half++) {
                int m = m0 + wm*32 + mt2*16 + gr + half*8;
                float v0 = acc[mt2][nt2][half*2+0] + b0;
                float v1 = acc[mt2][nt2][half*2+1] + b1;
                if (MODE==0) {
                    *(float2*)&Cout[(size_t)m*Nn+n] = make_float2(v0,v1);
                } else {
                    int part=n/DIM, rem=n-part*DIM, h=rem>>6, d=rem&63;
                    int bb=m>>9, tok=m&511;
                    size_t o = ((size_t)((bb*NHEAD+h)*NTOK+tok))*HD + d;
                    if (part==0)      *(float2*)&g_q[o]=make_float2(v0*ATTN_SCALE,v1*ATTN_SCALE);
                    else if (part==1) *(float2*)&g_k[o]=make_float2(v0,v1);
                    else              *(float2*)&g_v[o]=make_float2(v0,v1);
                }
            }
        }
    }
}

// ---- TF32 mma flash attention, pair-packed B frags ----
__global__ __launch_bounds__(256,2)
void attn_mma_kernel()
{
    __shared__ uint32_t Qs[8192];
    __shared__ uint32_t KVs[4096];   // [((np*8+ks)*32 + slot)*4 + 2*ntl + reg]

    const int tid=threadIdx.x, warp=tid>>5, lane=tid&31, l_l=lane&3;
    const int row0=blockIdx.x*128, h=blockIdx.y, b=blockIdx.z;
    const size_t base = ((size_t)(b*NHEAD+h))*NTOK*HD;
    const int rt = blockIdx.x*8 + warp;

#pragma unroll
    for (int u=0; u<8; u++) {
        int f4=tid+256*u, row=f4>>4, d0=(f4&15)*4;
        float4 q = *(const float4*)&g_q[base + (size_t)(row0+row)*HD + d0];
        int ks=d0>>3, dh=(d0>>2)&1, mt=row>>4, g=row&7, r8=(row>>3)&1;
        int sg=((ks&3)^(g>>1))&3;
        int ab=((mt*8+ks)*32+4*g)*4 + r8 + 2*dh;
        Qs[ab+((0^sg)<<2)]=f2tf32(q.x);
        Qs[ab+((1^sg)<<2)]=f2tf32(q.y);
        Qs[ab+((2^sg)<<2)]=f2tf32(q.z);
        Qs[ab+((3^sg)<<2)]=f2tf32(q.w);
    }

    float oacc[8][4];
#pragma unroll
    for(int i=0;i<8;i++)
#pragma unroll
        for(int j=0;j<4;j++) oacc[i][j]=0.f;
    float s0=0.f, s1=0.f;
    const int srcA = (lane&28)|(l_l>>1);

    for (int ch=0; ch<8; ch++) {
        const int c0=ch*64;
        __syncthreads();

        // K chunk -> pair-packed B-frag
#pragma unroll
        for (int u=0; u<4; u++) {
            int f4=tid+256*u, key=f4>>4, d0=(f4&15)*4;
            float4 kv = *(const float4*)&g_k[base + (size_t)(c0+key)*HD + d0];
            int ks=d0>>3, kh=(d0>>2)&1, nt=key>>3, np=nt>>1, ntl=nt&1, g=key&7;
            int sg=(((ks^np)&3)^(g>>1))&3;
            int bb=((np*8+ks)*32+4*g)*4 + 2*ntl + kh;
            KVs[bb+((0^sg)<<2)]=f2tf32(kv.x);
            KVs[bb+((1^sg)<<2)]=f2tf32(kv.y);
            KVs[bb+((2^sg)<<2)]=f2tf32(kv.z);
            KVs[bb+((3^sg)<<2)]=f2tf32(kv.w);
        }
        __syncthreads();

        float sf[8][4];
#pragma unroll
        for(int i=0;i<8;i++)
#pragma unroll
            for(int j=0;j<4;j++) sf[i][j]=0.f;
#pragma unroll
        for (int ks=0; ks<8; ks++) {
            int sa = lane ^ (((ks&3)^(lane>>3))&3);
            uint32_t a[4];
            *(uint4*)a = *(const uint4*)&Qs[((warp*8+ks)*32+sa)*4];
#pragma unroll
            for (int np=0; np<4; np++) {
                int sb = lane ^ ((((ks^np)&3)^(lane>>3))&3);
                uint4 bq = *(const uint4*)&KVs[((np*8+ks)*32+sb)*4];
                mma_tf32(sf[2*np+0],a,&bq.x);
                mma_tf32(sf[2*np+1],a,&bq.z);
            }
        }
        __syncthreads();

        // V chunk -> pair-packed B-frag
#pragma unroll
        for (int u=0; u<4; u++) {
            int f4=tid+256*u, key=f4>>4, d0=(f4&15)*4;
            float4 vv = *(const float4*)&g_v[base + (size_t)(c0+key)*HD + d0];
            float vq[4]={vv.x,vv.y,vv.z,vv.w};
            int kc=key>>3, lk=key&3, rg=(key>>2)&1;
            int nt=d0>>3, np=nt>>1, ntl=nt&1;
#pragma unroll
            for (int j=0; j<4; j++) {
                int g=(d0&7)+j;
                int sg=(((kc^np)&3)^(g>>1))&3;
                KVs[((np*8+kc)*32 + 4*g + (lk^sg))*4 + 2*ntl + rg] = f2tf32(vq[j]);
            }
        }

#pragma unroll
        for (int nt=0; nt<8; nt++) {
            float4 bf = *(const float4*)&g_biasp[
                ((((size_t)h*32+rt)*8+ch)*8+nt)*128 + lane*4];
            sf[nt][0]=__expf(sf[nt][0]+bf.x);
            sf[nt][1]=__expf(sf[nt][1]+bf.y);
            sf[nt][2]=__expf(sf[nt][2]+bf.z);
            sf[nt][3]=__expf(sf[nt][3]+bf.w);
            s0 += sf[nt][0]+sf[nt][1];
            s1 += sf[nt][2]+sf[nt][3];
        }
        __syncthreads();

#pragma unroll
        for (int kc=0; kc<8; kc++) {
            float c0v=sf[kc][0], c1v=sf[kc][1], c2v=sf[kc][2], c3v=sf[kc][3];
            float s00=__shfl_sync(0xffffffffu,c0v,srcA);
            float s01=__shfl_sync(0xffffffffu,c1v,srcA);
            float s10=__shfl_sync(0xffffffffu,c2v,srcA);
            float s11=__shfl_sync(0xffffffffu,c3v,srcA);
            float t00=__shfl_sync(0xffffffffu,c0v,srcA+2);
            float t01=__shfl_sync(0xffffffffu,c1v,srcA+2);
            float t10=__shfl_sync(0xffffffffu,c2v,srcA+2);
            float t11=__shfl_sync(0xffffffffu,c3v,srcA+2);
            bool odd = l_l & 1;
            uint32_t a[4];
            a[0]=f2tf32(odd?s01:s00); a[1]=f2tf32(odd?s11:s10);
            a[2]=f2tf32(odd?t01:t00); a[3]=f2tf32(odd?t11:t10);
#pragma unroll
            for (int np=0; np<4; np++) {
                int sb = lane ^ ((((kc^np)&3)^(lane>>3))&3);
                uint4 bq = *(const uint4*)&KVs[((np*8+kc)*32+sb)*4];
                mma_tf32(oacc[2*np+0],a,&bq.x);
                mma_tf32(oacc[2*np+1],a,&bq.z);
            }
        }
    }

    s0 += __shfl_xor_sync(0xffffffffu,s0,1);
    s0 += __shfl_xor_sync(0xffffffffu,s0,2);
    s1 += __shfl_xor_sync(0xffffffffu,s1,1);
    s1 += __shfl_xor_sync(0xffffffffu,s1,2);
    float i0=1.f/s0, i1=1.f/s1;
    int rowA = row0 + warp*16 + (lane>>2);
#pragma unroll
    for (int nt=0; nt<8; nt++) {
        int col = h*HD + nt*8 + 2*l_l;
        *(float2*)&g_attnout[((size_t)b*NTOK+rowA)*DIM + col] =
            make_float2(oacc[nt][0]*i0, oacc[nt][1]*i0);
        *(float2*)&g_attnout[((size_t)b*NTOK+rowA+8)*DIM + col] =
            make_float2(oacc[nt][2]*i1, oacc[nt][3]*i1);
    }
}

extern "C" void kernel_launch(void* const* d_in, const int* in_sizes, int n_in,
                              void* d_out, int out_size)
{
    const float* x     = (const float*)d_in[0];
    const float* Wqkv  = (const float*)d_in[1];
    const float* bqkv  = (const float*)d_in[2];
    const float* table = (const float*)d_in[3];
    const int*   idx   = (const int*)  d_in[4];
    const float* Wproj = (const float*)d_in[5];
    const float* bproj = (const float*)d_in[6];
    float* out = (float*)d_out;

    bias_gather_kernel<<<(NTOK*NTOK)/256, 256>>>(table, idx);

    gemm_tf32_kernel<1><<<dim3(QKV_N/128, MTOK/128), 256>>>(
        x, Wqkv, bqkv, nullptr, MTOK, QKV_N, DIM);

    attn_mma_kernel<<<dim3(NTOK/128, NHEAD, NBATCH), 256>>>();

    gemm_tf32_kernel<0><<<dim3(DIM/128, MTOK/128), 256>>>(
        nullptr, Wproj, bproj, out, MTOK, DIM, DIM);
}

// round 9
// speedup vs baseline: 1.0642x; 1.0642x over previous
#include <cuda_runtime.h>
#include <cstdint>

#define NHEAD 12
#define HD 64
#define NTOK 512
#define NBATCH 32
#define DIM 768
#define MTOK (NBATCH*NTOK)
#define QKV_N (3*DIM)
#define ATTN_SCALE 0.125f

__device__ float g_q[(size_t)NBATCH*NHEAD*NTOK*HD];
__device__ float g_k[(size_t)NBATCH*NHEAD*NTOK*HD];
__device__ float g_v[(size_t)NBATCH*NHEAD*NTOK*HD];
__device__ float g_biasp[(size_t)NHEAD*NTOK*NTOK];   // c-frag layout [h][rt][ch][nt][lane][reg]
__device__ float g_attnout[(size_t)MTOK*DIM];
// pre-rounded (tf32) operand copies
__device__ float g_xr[(size_t)MTOK*DIM];
__device__ float g_wr_qkv[(size_t)QKV_N*DIM];
__device__ float g_wr_proj[(size_t)DIM*DIM];

__device__ __forceinline__ uint32_t f2tf32(float x){
    uint32_t r; asm("cvt.rna.tf32.f32 %0, %1;" : "=r"(r) : "f"(x)); return r;
}
__device__ __forceinline__ float rnd32(float x){
    return __uint_as_float(f2tf32(x));
}
__device__ __forceinline__ void mma_tf32(float* c,const uint32_t* a,const uint32_t* b){
    asm volatile("mma.sync.aligned.m16n8k8.row.col.f32.tf32.tf32.f32 "
        "{%0,%1,%2,%3}, {%4,%5,%6,%7}, {%8,%9}, {%0,%1,%2,%3};"
        : "+f"(c[0]),"+f"(c[1]),"+f"(c[2]),"+f"(c[3])
        : "r"(a[0]),"r"(a[1]),"r"(a[2]),"r"(a[3]),"r"(b[0]),"r"(b[1]));
}

// ---- round-copy: dst = tf32_round(src), vectorized ----
__global__ void round_copy_kernel(const float* __restrict__ src,
                                  float* __restrict__ dst, int n4)
{
    int i = blockIdx.x*256 + threadIdx.x;
    if (i < n4) {
        float4 v = *(const float4*)&src[i*4];
        v.x = rnd32(v.x); v.y = rnd32(v.y); v.z = rnd32(v.z); v.w = rnd32(v.w);
        *(float4*)&dst[i*4] = v;
    }
}

// ---- bias gather into c-fragment layout ----
__global__ void bias_gather_kernel(const float* __restrict__ table,
                                   const int* __restrict__ idx)
{
    int e = blockIdx.x*256 + threadIdx.x;
    int rt=e>>13, kt=(e>>10)&7, nt=(e>>7)&7, lane=(e>>2)&31, reg=e&3;
    int g=lane>>2, l=lane&3;
    int row = rt*16 + g + 8*(reg>>1);
    int col = kt*64 + nt*8 + 2*l + (reg&1);
    int id = idx[row*NTOK + col];
    const float* t = table + (size_t)id*NHEAD;
#pragma unroll
    for (int h=0; h<NHEAD; h++)
        g_biasp[(size_t)h*262144 + e] = t[h];
}

// ---- TF32 GEMM, double-buffered, pre-rounded operands (no cvt in fill) ----
template<int MODE>
__global__ __launch_bounds__(256,2)
void gemm_tf32_kernel(const float* __restrict__ biasv, float* __restrict__ Cout,
                      int M, int Nn, int K)
{
    __shared__ uint32_t As[2][4096];
    __shared__ uint32_t Bs[2][4096];
    const float* A  = (MODE==0) ? g_attnout : g_xr;
    const float* Bw = (MODE==0) ? g_wr_proj : g_wr_qkv;
    const int tid=threadIdx.x, warp=tid>>5, lane=tid&31;
    const int wm=warp&3, wn=warp>>2;
    const int m0=blockIdx.y*128, n0=blockIdx.x*128;
    const int nT = K >> 5;

    float acc[2][8][4];
#pragma unroll
    for(int i=0;i<2;i++)
#pragma unroll
        for(int j=0;j<8;j++)
#pragma unroll
            for(int r=0;r<4;r++) acc[i][j][r]=0.f;

    uint4 av[4], bv[4];
#pragma unroll
    for (int u=0; u<4; u++) {
        int f4=tid+256*u, row=f4>>3, kq=f4&7;
        av[u] = *(const uint4*)&A [(size_t)(m0+row)*K + kq*4];
        bv[u] = *(const uint4*)&Bw[(size_t)(n0+row)*K + kq*4];
    }
#pragma unroll
    for (int u=0; u<4; u++) {
        int f4=tid+256*u, row=f4>>3, kq=f4&7, ks=kq>>1, kh=kq&1, g=row&7;
        {
            int mt=row>>4, r8=(row>>3)&1, sg=(ks^(g>>1))&3;
            int ab=((mt*4+ks)*32+4*g)*4 + r8 + 2*kh;
            As[0][ab+((0^sg)<<2)]=av[u].x;
            As[0][ab+((1^sg)<<2)]=av[u].y;
            As[0][ab+((2^sg)<<2)]=av[u].z;
            As[0][ab+((3^sg)<<2)]=av[u].w;
        }
        {
            int nt=row>>3, sg=(((ks^nt)&3)^(g>>1))&3;
            int bb=((nt*4+ks)*32+4*g)*2 + kh;
            Bs[0][bb+((0^sg)<<1)]=bv[u].x;
            Bs[0][bb+((1^sg)<<1)]=bv[u].y;
            Bs[0][bb+((2^sg)<<1)]=bv[u].z;
            Bs[0][bb+((3^sg)<<1)]=bv[u].w;
        }
    }
    __syncthreads();

    for (int t=0; t<nT; t++) {
        const int cur = t&1, nxt = cur^1;
        const bool hasNext = (t+1 < nT);
        if (hasNext) {
            int kt=(t+1)<<5;
#pragma unroll
            for (int u=0; u<4; u++) {
                int f4=tid+256*u, row=f4>>3, kq=f4&7;
                av[u] = *(const uint4*)&A [(size_t)(m0+row)*K + kt + kq*4];
                bv[u] = *(const uint4*)&Bw[(size_t)(n0+row)*K + kt + kq*4];
            }
        }
#pragma unroll
        for (int ks=0; ks<4; ks++) {
            int sa = lane ^ ((ks^(lane>>3))&3);
            uint32_t afr[2][4];
#pragma unroll
            for (int mt2=0; mt2<2; mt2++) {
                int mt=wm*2+mt2;
                *(uint4*)afr[mt2] = *(const uint4*)&As[cur][((mt*4+ks)*32+sa)*4];
            }
#pragma unroll
            for (int nt2=0; nt2<8; nt2++) {
                int nt=wn*8+nt2;
                int sb = lane ^ ((((ks^nt)&3)^(lane>>3))&3);
                uint32_t bfr[2];
                *(uint2*)bfr = *(const uint2*)&Bs[cur][((nt*4+ks)*32+sb)*2];
                mma_tf32(acc[0][nt2],afr[0],bfr);
                mma_tf32(acc[1][nt2],afr[1],bfr);
            }
        }
        if (hasNext) {
#pragma unroll
            for (int u=0; u<4; u++) {
                int f4=tid+256*u, row=f4>>3, kq=f4&7, ks=kq>>1, kh=kq&1, g=row&7;
                {
                    int mt=row>>4, r8=(row>>3)&1, sg=(ks^(g>>1))&3;
                    int ab=((mt*4+ks)*32+4*g)*4 + r8 + 2*kh;
                    As[nxt][ab+((0^sg)<<2)]=av[u].x;
                    As[nxt][ab+((1^sg)<<2)]=av[u].y;
                    As[nxt][ab+((2^sg)<<2)]=av[u].z;
                    As[nxt][ab+((3^sg)<<2)]=av[u].w;
                }
                {
                    int nt=row>>3, sg=(((ks^nt)&3)^(g>>1))&3;
                    int bb=((nt*4+ks)*32+4*g)*2 + kh;
                    Bs[nxt][bb+((0^sg)<<1)]=bv[u].x;
                    Bs[nxt][bb+((1^sg)<<1)]=bv[u].y;
                    Bs[nxt][bb+((2^sg)<<1)]=bv[u].z;
                    Bs[nxt][bb+((3^sg)<<1)]=bv[u].w;
                }
            }
        }
        __syncthreads();
    }

    const int gr=lane>>2, gl=lane&3;
#pragma unroll
    for (int mt2=0; mt2<2; mt2++) {
#pragma unroll
        for (int nt2=0; nt2<8; nt2++) {
            int n = n0 + wn*64 + nt2*8 + gl*2;
            float b0=biasv[n], b1=biasv[n+1];
#pragma unroll
            for (int half=0; half<2; half++) {
                int m = m0 + wm*32 + mt2*16 + gr + half*8;
                float v0 = acc[mt2][nt2][half*2+0] + b0;
                float v1 = acc[mt2][nt2][half*2+1] + b1;
                if (MODE==0) {
                    *(float2*)&Cout[(size_t)m*Nn+n] = make_float2(v0,v1);
                } else {
                    // pre-round for the attention kernel (q also pre-scaled;
                    // 0.125 is a power of two so scale commutes with rounding)
                    int part=n/DIM, rem=n-part*DIM, h=rem>>6, d=rem&63;
                    int bb=m>>9, tok=m&511;
                    size_t o = ((size_t)((bb*NHEAD+h)*NTOK+tok))*HD + d;
                    if (part==0)
                        *(float2*)&g_q[o]=make_float2(rnd32(v0*ATTN_SCALE),
                                                      rnd32(v1*ATTN_SCALE));
                    else if (part==1)
                        *(float2*)&g_k[o]=make_float2(rnd32(v0),rnd32(v1));
                    else
                        *(float2*)&g_v[o]=make_float2(rnd32(v0),rnd32(v1));
                }
            }
        }
    }
}

// ---- TF32 mma flash attention (R6 structure; operands pre-rounded) ----
__global__ __launch_bounds__(256,2)
void attn_mma_kernel()
{
    __shared__ uint32_t Qs[8192];
    __shared__ uint32_t KVs[4096];

    const int tid=threadIdx.x, warp=tid>>5, lane=tid&31, l_l=lane&3;
    const int row0=blockIdx.x*128, h=blockIdx.y, b=blockIdx.z;
    const size_t base = ((size_t)(b*NHEAD+h))*NTOK*HD;
    const int rt = blockIdx.x*8 + warp;

#pragma unroll
    for (int u=0; u<8; u++) {
        int f4=tid+256*u, row=f4>>4, d0=(f4&15)*4;
        uint4 q = *(const uint4*)&g_q[base + (size_t)(row0+row)*HD + d0];
        int ks=d0>>3, dh=(d0>>2)&1, mt=row>>4, g=row&7, r8=(row>>3)&1;
        int sg=((ks&3)^(g>>1))&3;
        int ab=((mt*8+ks)*32+4*g)*4 + r8 + 2*dh;
        Qs[ab+((0^sg)<<2)]=q.x;
        Qs[ab+((1^sg)<<2)]=q.y;
        Qs[ab+((2^sg)<<2)]=q.z;
        Qs[ab+((3^sg)<<2)]=q.w;
    }

    float oacc[8][4];
#pragma unroll
    for(int i=0;i<8;i++)
#pragma unroll
        for(int j=0;j<4;j++) oacc[i][j]=0.f;
    float s0=0.f, s1=0.f;
    const int srcA = (lane&28)|(l_l>>1);

    for (int ch=0; ch<8; ch++) {
        const int c0=ch*64;
        __syncthreads();

#pragma unroll
        for (int u=0; u<4; u++) {
            int f4=tid+256*u, key=f4>>4, d0=(f4&15)*4;
            uint4 kv = *(const uint4*)&g_k[base + (size_t)(c0+key)*HD + d0];
            int ks=d0>>3, kh=(d0>>2)&1, nt=key>>3, g=key&7;
            int sg=(((ks^nt)&3)^(g>>1))&3;
            int bb=((nt*8+ks)*32+4*g)*2 + kh;
            KVs[bb+((0^sg)<<1)]=kv.x;
            KVs[bb+((1^sg)<<1)]=kv.y;
            KVs[bb+((2^sg)<<1)]=kv.z;
            KVs[bb+((3^sg)<<1)]=kv.w;
        }
        __syncthreads();

        float sf[8][4];
#pragma unroll
        for(int i=0;i<8;i++)
#pragma unroll
            for(int j=0;j<4;j++) sf[i][j]=0.f;
#pragma unroll
        for (int ks=0; ks<8; ks++) {
            int sa = lane ^ (((ks&3)^(lane>>3))&3);
            uint32_t a[4];
            *(uint4*)a = *(const uint4*)&Qs[((warp*8+ks)*32+sa)*4];
#pragma unroll
            for (int nt=0; nt<8; nt++) {
                int sb = lane ^ ((((ks^nt)&3)^(lane>>3))&3);
                uint32_t bb[2];
                *(uint2*)bb = *(const uint2*)&KVs[((nt*8+ks)*32+sb)*2];
                mma_tf32(sf[nt],a,bb);
            }
        }
        __syncthreads();

#pragma unroll
        for (int u=0; u<4; u++) {
            int f4=tid+256*u, key=f4>>4, d0=(f4&15)*4;
            uint4 vv = *(const uint4*)&g_v[base + (size_t)(c0+key)*HD + d0];
            uint32_t vq[4]={vv.x,vv.y,vv.z,vv.w};
            int kc=key>>3, lk=key&3, rg=(key>>2)&1, nt=d0>>3;
#pragma unroll
            for (int j=0; j<4; j++) {
                int g=(d0&7)+j;
                int sg=(((kc^nt)&3)^(g>>1))&3;
                KVs[((nt*8+kc)*32 + 4*g + (lk^sg))*2 + rg] = vq[j];
            }
        }

#pragma unroll
        for (int nt=0; nt<8; nt++) {
            float4 bf = *(const float4*)&g_biasp[
                ((((size_t)h*32+rt)*8+ch)*8+nt)*128 + lane*4];
            sf[nt][0]=__expf(sf[nt][0]+bf.x);
            sf[nt][1]=__expf(sf[nt][1]+bf.y);
            sf[nt][2]=__expf(sf[nt][2]+bf.z);
            sf[nt][3]=__expf(sf[nt][3]+bf.w);
            s0 += sf[nt][0]+sf[nt][1];
            s1 += sf[nt][2]+sf[nt][3];
        }
        __syncthreads();

#pragma unroll
        for (int kc=0; kc<8; kc++) {
            float c0v=sf[kc][0], c1v=sf[kc][1], c2v=sf[kc][2], c3v=sf[kc][3];
            float s00=__shfl_sync(0xffffffffu,c0v,srcA);
            float s01=__shfl_sync(0xffffffffu,c1v,srcA);
            float s10=__shfl_sync(0xffffffffu,c2v,srcA);
            float s11=__shfl_sync(0xffffffffu,c3v,srcA);
            float t00=__shfl_sync(0xffffffffu,c0v,srcA+2);
            float t01=__shfl_sync(0xffffffffu,c1v,srcA+2);
            float t10=__shfl_sync(0xffffffffu,c2v,srcA+2);
            float t11=__shfl_sync(0xffffffffu,c3v,srcA+2);
            bool odd = l_l & 1;
            uint32_t a[4];
            a[0]=f2tf32(odd?s01:s00); a[1]=f2tf32(odd?s11:s10);
            a[2]=f2tf32(odd?t01:t00); a[3]=f2tf32(odd?t11:t10);
#pragma unroll
            for (int nt=0; nt<8; nt++) {
                int sb = lane ^ ((((kc^nt)&3)^(lane>>3))&3);
                uint32_t bb[2];
                *(uint2*)bb = *(const uint2*)&KVs[((nt*8+kc)*32+sb)*2];
                mma_tf32(oacc[nt],a,bb);
            }
        }
    }

    s0 += __shfl_xor_sync(0xffffffffu,s0,1);
    s0 += __shfl_xor_sync(0xffffffffu,s0,2);
    s1 += __shfl_xor_sync(0xffffffffu,s1,1);
    s1 += __shfl_xor_sync(0xffffffffu,s1,2);
    float i0=1.f/s0, i1=1.f/s1;
    int rowA = row0 + warp*16 + (lane>>2);
    // store pre-rounded (tf32) attnout so the proj GEMM fill needs no cvt
#pragma unroll
    for (int nt=0; nt<8; nt++) {
        int col = h*HD + nt*8 + 2*l_l;
        *(float2*)&g_attnout[((size_t)b*NTOK+rowA)*DIM + col] =
            make_float2(rnd32(oacc[nt][0]*i0), rnd32(oacc[nt][1]*i0));
        *(float2*)&g_attnout[((size_t)b*NTOK+rowA+8)*DIM + col] =
            make_float2(rnd32(oacc[nt][2]*i1), rnd32(oacc[nt][3]*i1));
    }
}

extern "C" void kernel_launch(void* const* d_in, const int* in_sizes, int n_in,
                              void* d_out, int out_size)
{
    const float* x     = (const float*)d_in[0];
    const float* Wqkv  = (const float*)d_in[1];
    const float* bqkv  = (const float*)d_in[2];
    const float* table = (const float*)d_in[3];
    const int*   idx   = (const int*)  d_in[4];
    const float* Wproj = (const float*)d_in[5];
    const float* bproj = (const float*)d_in[6];
    float* out = (float*)d_out;

    float* xr; float* wqkvr; float* wprojr;
    cudaGetSymbolAddress((void**)&xr,     g_xr);
    cudaGetSymbolAddress((void**)&wqkvr,  g_wr_qkv);
    cudaGetSymbolAddress((void**)&wprojr, g_wr_proj);

    round_copy_kernel<<<(MTOK*DIM/4 + 255)/256, 256>>>(x, xr, MTOK*DIM/4);
    round_copy_kernel<<<(QKV_N*DIM/4 + 255)/256, 256>>>(Wqkv, wqkvr, QKV_N*DIM/4);
    round_copy_kernel<<<(DIM*DIM/4 + 255)/256, 256>>>(Wproj, wprojr, DIM*DIM/4);

    bias_gather_kernel<<<(NTOK*NTOK)/256, 256>>>(table, idx);

    gemm_tf32_kernel<1><<<dim3(QKV_N/128, MTOK/128), 256>>>(bqkv, nullptr,
                                                            MTOK, QKV_N, DIM);

    attn_mma_kernel<<<dim3(NTOK/128, NHEAD, NBATCH), 256>>>();

    gemm_tf32_kernel<0><<<dim3(DIM/128, MTOK/128), 256>>>(bproj, out,
                                                          MTOK, DIM, DIM);
}

// round 10
// speedup vs baseline: 1.9304x; 1.8140x over previous
#include <cuda_runtime.h>
#include <cuda_fp16.h>
#include <cstdint>

#define NHEAD 12
#define HD 64
#define NTOK 512
#define NBATCH 32
#define DIM 768
#define MTOK (NBATCH*NTOK)
#define QKV_N (3*DIM)
#define ATTN_SCALE 0.125f

__device__ __half g_q[(size_t)NBATCH*NHEAD*NTOK*HD];
__device__ __half g_k[(size_t)NBATCH*NHEAD*NTOK*HD];
__device__ __half g_v[(size_t)NBATCH*NHEAD*NTOK*HD];
__device__ float  g_biasp[(size_t)NHEAD*NTOK*NTOK];  // c-frag layout [h][rt][ch][nt][lane][reg]
__device__ __half g_attnout[(size_t)MTOK*DIM];
__device__ __half g_xr[(size_t)MTOK*DIM];
__device__ __half g_wr_qkv[(size_t)QKV_N*DIM];
__device__ __half g_wr_proj[(size_t)DIM*DIM];

__device__ __forceinline__ uint32_t pack_h2(float lo, float hi){
    __half2 h = __floats2half2_rn(lo, hi);
    return *(uint32_t*)&h;
}
__device__ __forceinline__ void mma_f16(float* c, const uint32_t* a, const uint32_t* b){
    asm volatile("mma.sync.aligned.m16n8k16.row.col.f32.f16.f16.f32 "
        "{%0,%1,%2,%3}, {%4,%5,%6,%7}, {%8,%9}, {%0,%1,%2,%3};"
        : "+f"(c[0]),"+f"(c[1]),"+f"(c[2]),"+f"(c[3])
        : "r"(a[0]),"r"(a[1]),"r"(a[2]),"r"(a[3]),"r"(b[0]),"r"(b[1]));
}

// ---- float -> half copy ----
__global__ void half_copy_kernel(const float* __restrict__ src,
                                 __half* __restrict__ dst, int n4)
{
    int i = blockIdx.x*256 + threadIdx.x;
    if (i < n4) {
        float4 v = *(const float4*)&src[i*4];
        uint2 o;
        o.x = pack_h2(v.x, v.y);
        o.y = pack_h2(v.z, v.w);
        *(uint2*)(dst + (size_t)i*4) = o;
    }
}

// ---- bias gather into c-fragment layout (fp32) ----
__global__ void bias_gather_kernel(const float* __restrict__ table,
                                   const int* __restrict__ idx)
{
    int e = blockIdx.x*256 + threadIdx.x;
    int rt=e>>13, kt=(e>>10)&7, nt=(e>>7)&7, lane=(e>>2)&31, reg=e&3;
    int g=lane>>2, l=lane&3;
    int row = rt*16 + g + 8*(reg>>1);
    int col = kt*64 + nt*8 + 2*l + (reg&1);
    int id = idx[row*NTOK + col];
    const float* t = table + (size_t)id*NHEAD;
#pragma unroll
    for (int h=0; h<NHEAD; h++)
        g_biasp[(size_t)h*262144 + e] = t[h];
}

// ---- FP16 GEMM, BK=64, double-buffered: C = A @ Bw^T + bias ----
// A-frag tile (m16,k16): word (g*4+l)*4 + reg, reg = rh + 2*kh (kh = k>=8)
// B-frag tile (n8,k16):  word (g*4+l)*2 + reg, reg = k>=8, l = (k>>1)&3
template<int MODE>
__global__ __launch_bounds__(256,2)
void gemm_f16_kernel(const float* __restrict__ biasv, float* __restrict__ Cout,
                     int M, int Nn, int K)
{
    __shared__ uint32_t As[2][4096];
    __shared__ uint32_t Bs[2][4096];
    const __half* A  = (MODE==0) ? g_attnout : g_xr;
    const __half* Bw = (MODE==0) ? g_wr_proj : g_wr_qkv;
    const int tid=threadIdx.x, warp=tid>>5, lane=tid&31;
    const int wm=warp&3, wn=warp>>2;
    const int m0=blockIdx.y*128, n0=blockIdx.x*128;
    const int nT = K >> 6;

    float acc[2][8][4];
#pragma unroll
    for(int i=0;i<2;i++)
#pragma unroll
        for(int j=0;j<8;j++)
#pragma unroll
            for(int r=0;r<4;r++) acc[i][j][r]=0.f;

    uint4 av[4], bv[4];
#pragma unroll
    for (int u=0; u<4; u++) {
        int f4=tid+256*u, row=f4>>3, ko=f4&7;
        av[u] = *(const uint4*)(A  + (size_t)(m0+row)*K + ko*8);
        bv[u] = *(const uint4*)(Bw + (size_t)(n0+row)*K + ko*8);
    }
#pragma unroll
    for (int u=0; u<4; u++) {
        int f4=tid+256*u, row=f4>>3, ko=f4&7, ks=ko>>1, kh=ko&1, g=row&7;
        {
            int mt=row>>4, rh=(row>>3)&1, sg=(ks^(g>>1))&3;
            int ab=(mt*4+ks)*128 + 16*g + rh + 2*kh;
            As[0][ab+4*(0^sg)]=av[u].x; As[0][ab+4*(1^sg)]=av[u].y;
            As[0][ab+4*(2^sg)]=av[u].z; As[0][ab+4*(3^sg)]=av[u].w;
        }
        {
            int nt=row>>3, sg=(((ks^nt)&3)^(g>>1))&3;
            int bb=(nt*4+ks)*64 + 8*g + kh;
            Bs[0][bb+2*(0^sg)]=bv[u].x; Bs[0][bb+2*(1^sg)]=bv[u].y;
            Bs[0][bb+2*(2^sg)]=bv[u].z; Bs[0][bb+2*(3^sg)]=bv[u].w;
        }
    }
    __syncthreads();

    for (int t=0; t<nT; t++) {
        const int cur = t&1, nxt = cur^1;
        const bool hasNext = (t+1 < nT);
        if (hasNext) {
            int kt=(t+1)<<6;
#pragma unroll
            for (int u=0; u<4; u++) {
                int f4=tid+256*u, row=f4>>3, ko=f4&7;
                av[u] = *(const uint4*)(A  + (size_t)(m0+row)*K + kt + ko*8);
                bv[u] = *(const uint4*)(Bw + (size_t)(n0+row)*K + kt + ko*8);
            }
        }
#pragma unroll
        for (int ks=0; ks<4; ks++) {
            int sa = lane ^ ((ks^(lane>>3))&3);
            uint32_t afr[2][4];
#pragma unroll
            for (int mt2=0; mt2<2; mt2++) {
                int mt=wm*2+mt2;
                *(uint4*)afr[mt2] = *(const uint4*)&As[cur][(mt*4+ks)*128 + 4*sa];
            }
#pragma unroll
            for (int nt2=0; nt2<8; nt2++) {
                int nt=wn*8+nt2;
                int sb = lane ^ ((((ks^nt)&3)^(lane>>3))&3);
                uint32_t bfr[2];
                *(uint2*)bfr = *(const uint2*)&Bs[cur][(nt*4+ks)*64 + 2*sb];
                mma_f16(acc[0][nt2],afr[0],bfr);
                mma_f16(acc[1][nt2],afr[1],bfr);
            }
        }
        if (hasNext) {
#pragma unroll
            for (int u=0; u<4; u++) {
                int f4=tid+256*u, row=f4>>3, ko=f4&7, ks=ko>>1, kh=ko&1, g=row&7;
                {
                    int mt=row>>4, rh=(row>>3)&1, sg=(ks^(g>>1))&3;
                    int ab=(mt*4+ks)*128 + 16*g + rh + 2*kh;
                    As[nxt][ab+4*(0^sg)]=av[u].x; As[nxt][ab+4*(1^sg)]=av[u].y;
                    As[nxt][ab+4*(2^sg)]=av[u].z; As[nxt][ab+4*(3^sg)]=av[u].w;
                }
                {
                    int nt=row>>3, sg=(((ks^nt)&3)^(g>>1))&3;
                    int bb=(nt*4+ks)*64 + 8*g + kh;
                    Bs[nxt][bb+2*(0^sg)]=bv[u].x; Bs[nxt][bb+2*(1^sg)]=bv[u].y;
                    Bs[nxt][bb+2*(2^sg)]=bv[u].z; Bs[nxt][bb+2*(3^sg)]=bv[u].w;
                }
            }
        }
        __syncthreads();
    }

    const int gr=lane>>2, gl=lane&3;
#pragma unroll
    for (int mt2=0; mt2<2; mt2++) {
#pragma unroll
        for (int nt2=0; nt2<8; nt2++) {
            int n = n0 + wn*64 + nt2*8 + gl*2;
            float b0=biasv[n], b1=biasv[n+1];
#pragma unroll
            for (int half_=0; half_<2; half_++) {
                int m = m0 + wm*32 + mt2*16 + gr + half_*8;
                float v0 = acc[mt2][nt2][half_*2+0] + b0;
                float v1 = acc[mt2][nt2][half_*2+1] + b1;
                if (MODE==0) {
                    *(float2*)&Cout[(size_t)m*Nn+n] = make_float2(v0,v1);
                } else {
                    int part=n/DIM, rem=n-part*DIM, h=rem>>6, d=rem&63;
                    int bb=m>>9, tok=m&511;
                    size_t o = ((size_t)((bb*NHEAD+h)*NTOK+tok))*HD + d;
                    uint32_t pq = pack_h2(v0*ATTN_SCALE, v1*ATTN_SCALE);
                    uint32_t pv = pack_h2(v0, v1);
                    if (part==0)      *(uint32_t*)(g_q+o) = pq;
                    else if (part==1) *(uint32_t*)(g_k+o) = pv;
                    else              *(uint32_t*)(g_v+o) = pv;
                }
            }
        }
    }
}

// ---- FP16 mma flash attention: 128 q-rows/block, 64-key chunks ----
__global__ __launch_bounds__(256,2)
void attn_mma_kernel()
{
    __shared__ uint32_t Qs[4096];    // A-frag tiles (mt=warp, ksec 0..3)
    __shared__ uint32_t KVs[2048];   // B-frag tiles (nt 0..7, ksec 0..3), K/V shared

    const int tid=threadIdx.x, warp=tid>>5, lane=tid&31, l_l=lane&3;
    const int row0=blockIdx.x*128, h=blockIdx.y, b=blockIdx.z;
    const size_t base = ((size_t)(b*NHEAD+h))*NTOK*HD;
    const int rt = blockIdx.x*8 + warp;

    // Q tile -> A-frag layout
#pragma unroll
    for (int u=0; u<4; u++) {
        int f4=tid+256*u, row=f4>>3, ko=f4&7;
        uint4 q = *(const uint4*)(g_q + base + (size_t)(row0+row)*HD + ko*8);
        int ks=ko>>1, kh=ko&1, mt=row>>4, g=row&7, rh=(row>>3)&1;
        int sg=(ks^(g>>1))&3;
        int ab=(mt*4+ks)*128 + 16*g + rh + 2*kh;
        Qs[ab+4*(0^sg)]=q.x; Qs[ab+4*(1^sg)]=q.y;
        Qs[ab+4*(2^sg)]=q.z; Qs[ab+4*(3^sg)]=q.w;
    }

    float oacc[8][4];
#pragma unroll
    for(int i=0;i<8;i++)
#pragma unroll
        for(int j=0;j<4;j++) oacc[i][j]=0.f;
    float s0=0.f, s1=0.f;

    for (int ch=0; ch<8; ch++) {
        const int c0=ch*64;
        __syncthreads();                 // prev PV done with KVs

        // K chunk -> B-frag (n = key, k = d)
#pragma unroll
        for (int u=0; u<2; u++) {
            int f4=tid+256*u, key=f4>>3, ko=f4&7;
            uint4 kv = *(const uint4*)(g_k + base + (size_t)(c0+key)*HD + ko*8);
            int ks=ko>>1, kh=ko&1, nt=key>>3, g=key&7;
            int sg=(((ks^nt)&3)^(g>>1))&3;
            int bb=(nt*4+ks)*64 + 8*g + kh;
            KVs[bb+2*(0^sg)]=kv.x; KVs[bb+2*(1^sg)]=kv.y;
            KVs[bb+2*(2^sg)]=kv.z; KVs[bb+2*(3^sg)]=kv.w;
        }
        __syncthreads();

        // S = Q @ K^T (warp: 16 x 64)
        float sf[8][4];
#pragma unroll
        for(int i=0;i<8;i++)
#pragma unroll
            for(int j=0;j<4;j++) sf[i][j]=0.f;
#pragma unroll
        for (int ks=0; ks<4; ks++) {
            int sa = lane ^ ((ks^(lane>>3))&3);
            uint32_t a[4];
            *(uint4*)a = *(const uint4*)&Qs[(warp*4+ks)*128 + 4*sa];
#pragma unroll
            for (int nt=0; nt<8; nt++) {
                int sb = lane ^ ((((ks^nt)&3)^(lane>>3))&3);
                uint32_t bb[2];
                *(uint2*)bb = *(const uint2*)&KVs[(nt*4+ks)*64 + 2*sb];
                mma_f16(sf[nt],a,bb);
            }
        }
        __syncthreads();                 // all warps done reading K

        // V chunk -> B-frag (n = d, k = key); scalar half stores
#pragma unroll
        for (int u=0; u<2; u++) {
            int f4=tid+256*u, key=f4>>3, d0=(f4&7)*8;
            uint4 vv = *(const uint4*)(g_v + base + (size_t)(c0+key)*HD + d0);
            const __half* vh = (const __half*)&vv;
            int nt=d0>>3, kcs=key>>4, reg=(key>>3)&1, l=(key>>1)&3, par=key&1;
            int wb = (nt*4+kcs)*64 + reg;
#pragma unroll
            for (int j=0; j<8; j++) {
                int sg=(((kcs^nt)&3)^(j>>1))&3;
                ((__half*)KVs)[(wb + 8*j + 2*(l^sg))*2 + par] = vh[j];
            }
        }

        // P = exp(S + bias); row sums
#pragma unroll
        for (int nt=0; nt<8; nt++) {
            float4 bf = *(const float4*)&g_biasp[
                ((((size_t)h*32+rt)*8+ch)*8+nt)*128 + lane*4];
            sf[nt][0]=__expf(sf[nt][0]+bf.x);
            sf[nt][1]=__expf(sf[nt][1]+bf.y);
            sf[nt][2]=__expf(sf[nt][2]+bf.z);
            sf[nt][3]=__expf(sf[nt][3]+bf.w);
            s0 += sf[nt][0]+sf[nt][1];
            s1 += sf[nt][2]+sf[nt][3];
        }
        __syncthreads();                 // V visible

        // O += P @ V ; a-frags are just packed c-frags (no shfl!)
#pragma unroll
        for (int kcs=0; kcs<4; kcs++) {
            uint32_t a[4];
            a[0] = pack_h2(sf[2*kcs  ][0], sf[2*kcs  ][1]);
            a[1] = pack_h2(sf[2*kcs  ][2], sf[2*kcs  ][3]);
            a[2] = pack_h2(sf[2*kcs+1][0], sf[2*kcs+1][1]);
            a[3] = pack_h2(sf[2*kcs+1][2], sf[2*kcs+1][3]);
#pragma unroll
            for (int nt=0; nt<8; nt++) {
                int sb = lane ^ ((((kcs^nt)&3)^(lane>>3))&3);
                uint32_t bb[2];
                *(uint2*)bb = *(const uint2*)&KVs[(nt*4+kcs)*64 + 2*sb];
                mma_f16(oacc[nt],a,bb);
            }
        }
    }

    s0 += __shfl_xor_sync(0xffffffffu,s0,1);
    s0 += __shfl_xor_sync(0xffffffffu,s0,2);
    s1 += __shfl_xor_sync(0xffffffffu,s1,1);
    s1 += __shfl_xor_sync(0xffffffffu,s1,2);
    float i0=1.f/s0, i1=1.f/s1;
    int rowA = row0 + warp*16 + (lane>>2);
#pragma unroll
    for (int nt=0; nt<8; nt++) {
        int col = h*HD + nt*8 + 2*l_l;
        *(uint32_t*)(g_attnout + ((size_t)b*NTOK+rowA)*DIM + col) =
            pack_h2(oacc[nt][0]*i0, oacc[nt][1]*i0);
        *(uint32_t*)(g_attnout + ((size_t)b*NTOK+rowA+8)*DIM + col) =
            pack_h2(oacc[nt][2]*i1, oacc[nt][3]*i1);
    }
}

extern "C" void kernel_launch(void* const* d_in, const int* in_sizes, int n_in,
                              void* d_out, int out_size)
{
    const float* x     = (const float*)d_in[0];
    const float* Wqkv  = (const float*)d_in[1];
    const float* bqkv  = (const float*)d_in[2];
    const float* table = (const float*)d_in[3];
    const int*   idx   = (const int*)  d_in[4];
    const float* Wproj = (const float*)d_in[5];
    const float* bproj = (const float*)d_in[6];
    float* out = (float*)d_out;

    __half* xr; __half* wqkvr; __half* wprojr;
    cudaGetSymbolAddress((void**)&xr,     g_xr);
    cudaGetSymbolAddress((void**)&wqkvr,  g_wr_qkv);
    cudaGetSymbolAddress((void**)&wprojr, g_wr_proj);

    half_copy_kernel<<<(MTOK*DIM/4 + 255)/256, 256>>>(x, xr, MTOK*DIM/4);
    half_copy_kernel<<<(QKV_N*DIM/4 + 255)/256, 256>>>(Wqkv, wqkvr, QKV_N*DIM/4);
    half_copy_kernel<<<(DIM*DIM/4 + 255)/256, 256>>>(Wproj, wprojr, DIM*DIM/4);

    bias_gather_kernel<<<(NTOK*NTOK)/256, 256>>>(table, idx);

    gemm_f16_kernel<1><<<dim3(QKV_N/128, MTOK/128), 256>>>(bqkv, nullptr,
                                                           MTOK, QKV_N, DIM);

    attn_mma_kernel<<<dim3(NTOK/128, NHEAD, NBATCH), 256>>>();

    gemm_f16_kernel<0><<<dim3(DIM/128, MTOK/128), 256>>>(bproj, out,
                                                         MTOK, DIM, DIM);
}

// round 11
// speedup vs baseline: 2.3544x; 1.2196x over previous
#include <cuda_runtime.h>
#include <cuda_fp16.h>
#include <cstdint>

#define NHEAD 12
#define HD 64
#define NTOK 512
#define NBATCH 32
#define DIM 768
#define MTOK (NBATCH*NTOK)
#define QKV_N (3*DIM)
#define ATTN_SCALE 0.125f

__device__ __half g_q[(size_t)NBATCH*NHEAD*NTOK*HD];
__device__ __half g_k[(size_t)NBATCH*NHEAD*NTOK*HD];
__device__ __half g_v[(size_t)NBATCH*NHEAD*NTOK*HD];
__device__ float  g_biasp[(size_t)NHEAD*NTOK*NTOK];  // c-frag layout
__device__ __half g_attnout[(size_t)MTOK*DIM];
__device__ __half g_xr[(size_t)MTOK*DIM];
__device__ __half g_wr_qkv[(size_t)QKV_N*DIM];
__device__ __half g_wr_proj[(size_t)DIM*DIM];

__device__ __forceinline__ uint32_t pack_h2(float lo, float hi){
    __half2 h = __floats2half2_rn(lo, hi);
    return *(uint32_t*)&h;
}
__device__ __forceinline__ void mma_f16(float* c, const uint32_t* a, const uint32_t* b){
    asm volatile("mma.sync.aligned.m16n8k16.row.col.f32.f16.f16.f32 "
        "{%0,%1,%2,%3}, {%4,%5,%6,%7}, {%8,%9}, {%0,%1,%2,%3};"
        : "+f"(c[0]),"+f"(c[1]),"+f"(c[2]),"+f"(c[3])
        : "r"(a[0]),"r"(a[1]),"r"(a[2]),"r"(a[3]),"r"(b[0]),"r"(b[1]));
}
__device__ __forceinline__ uint32_t smem_addr_of(const void* p){
    return (uint32_t)__cvta_generic_to_shared(p);
}
__device__ __forceinline__ void cp_async16(uint32_t dst, const void* src){
    asm volatile("cp.async.cg.shared.global [%0], [%1], 16;" :: "r"(dst), "l"(src));
}
__device__ __forceinline__ void cp_commit(){
    asm volatile("cp.async.commit_group;");
}
template<int N> __device__ __forceinline__ void cp_wait(){
    asm volatile("cp.async.wait_group %0;" :: "n"(N));
}
__device__ __forceinline__ void ldsm_x4(uint32_t* r, uint32_t addr){
    asm volatile("ldmatrix.sync.aligned.m8n8.x4.shared.b16 {%0,%1,%2,%3}, [%4];"
        : "=r"(r[0]),"=r"(r[1]),"=r"(r[2]),"=r"(r[3]) : "r"(addr));
}

// ---- float -> half copy ----
__global__ void half_copy_kernel(const float* __restrict__ src,
                                 __half* __restrict__ dst, int n4)
{
    int i = blockIdx.x*256 + threadIdx.x;
    if (i < n4) {
        float4 v = *(const float4*)&src[i*4];
        uint2 o;
        o.x = pack_h2(v.x, v.y);
        o.y = pack_h2(v.z, v.w);
        *(uint2*)(dst + (size_t)i*4) = o;
    }
}

// ---- bias gather into c-fragment layout ----
__global__ void bias_gather_kernel(const float* __restrict__ table,
                                   const int* __restrict__ idx)
{
    int e = blockIdx.x*256 + threadIdx.x;
    int rt=e>>13, kt=(e>>10)&7, nt=(e>>7)&7, lane=(e>>2)&31, reg=e&3;
    int g=lane>>2, l=lane&3;
    int row = rt*16 + g + 8*(reg>>1);
    int col = kt*64 + nt*8 + 2*l + (reg&1);
    int id = idx[row*NTOK + col];
    const float* t = table + (size_t)id*NHEAD;
#pragma unroll
    for (int h=0; h<NHEAD; h++)
        g_biasp[(size_t)h*262144 + e] = t[h];
}

// ---- FP16 GEMM: cp.async fill + ldmatrix mainloop, BK=64, 2-stage ----
// Smem tile: 128 rows x 128 B (64 halves); byte = row*128 + (c ^ (row&7))*16.
template<int MODE>
__global__ __launch_bounds__(256,2)
void gemm_f16_kernel(const float* __restrict__ biasv, float* __restrict__ Cout,
                     int M, int Nn, int K)
{
    __shared__ __align__(128) __half As[2][128*64];
    __shared__ __align__(128) __half Bs[2][128*64];
    const __half* A  = (MODE==0) ? g_attnout : g_xr;
    const __half* Bw = (MODE==0) ? g_wr_proj : g_wr_qkv;
    const int tid=threadIdx.x, warp=tid>>5, lane=tid&31;
    const int wm=warp&3, wn=warp>>2;
    const int m0=blockIdx.y*128, n0=blockIdx.x*128;
    const int nT = K >> 6;

    const uint32_t aBase = smem_addr_of(As);
    const uint32_t bBase = smem_addr_of(Bs);

    // fill assignment: 4 chunks of A + 4 of B per thread per tile
    int frow[4]; uint32_t fdst[4];
#pragma unroll
    for (int u=0; u<4; u++) {
        int f = tid + 256*u;            // 0..1023
        int row = f>>3, c = f&7;
        frow[u] = row;
        fdst[u] = (uint32_t)(row*128 + ((c ^ (row&7))<<4));
    }

    // ldmatrix per-thread row/addr invariants
    const int qa = lane>>3;             // A quad: 0..3
    const int ra = lane&7;
    int mrow[2];                        // per mt2
#pragma unroll
    for (int mt2=0; mt2<2; mt2++)
        mrow[mt2] = (wm*2+mt2)*16 + (qa&1)*8 + ra;
    const int akc = qa>>1;              // k-chunk half (0/1) within k16
    int nrow[4][1];                     // per np2: n row for this lane
    const int ntsel = (lane>>4)&1, bkc = (lane>>3)&1;
#pragma unroll
    for (int np2=0; np2<4; np2++)
        nrow[np2][0] = (wn*8 + np2*2 + ntsel)*8 + ra;

    float acc[2][8][4];
#pragma unroll
    for(int i=0;i<2;i++)
#pragma unroll
        for(int j=0;j<8;j++)
#pragma unroll
            for(int r=0;r<4;r++) acc[i][j][r]=0.f;

    // prologue: async-fill stage 0
#pragma unroll
    for (int u=0; u<4; u++) {
        int c = (tid+256*u)&7;
        cp_async16(aBase + fdst[u], A  + (size_t)(m0+frow[u])*K + c*8);
        cp_async16(bBase + fdst[u], Bw + (size_t)(n0+frow[u])*K + c*8);
    }
    cp_commit();

    for (int t=0; t<nT; t++) {
        const int cur = t&1, nxt = cur^1;
        if (t+1 < nT) {
            int kt = (t+1)<<6;
#pragma unroll
            for (int u=0; u<4; u++) {
                int c = (tid+256*u)&7;
                cp_async16(aBase + nxt*16384 + fdst[u],
                           A  + (size_t)(m0+frow[u])*K + kt + c*8);
                cp_async16(bBase + nxt*16384 + fdst[u],
                           Bw + (size_t)(n0+frow[u])*K + kt + c*8);
            }
            cp_commit();
            cp_wait<1>();
        } else {
            cp_wait<0>();
        }
        __syncthreads();

        const uint32_t aS = aBase + cur*16384;
        const uint32_t bS = bBase + cur*16384;
#pragma unroll
        for (int ks=0; ks<4; ks++) {
            uint32_t afr[2][4];
#pragma unroll
            for (int mt2=0; mt2<2; mt2++) {
                int m = mrow[mt2];
                int kc = ks*2 + akc;
                ldsm_x4(afr[mt2], aS + m*128 + ((kc ^ (m&7))<<4));
            }
#pragma unroll
            for (int np2=0; np2<4; np2++) {
                int n = nrow[np2][0];
                int kc = ks*2 + bkc;
                uint32_t bq[4];
                ldsm_x4(bq, bS + n*128 + ((kc ^ (n&7))<<4));
#pragma unroll
                for (int mt2=0; mt2<2; mt2++) {
                    mma_f16(acc[mt2][np2*2+0], afr[mt2], &bq[0]);
                    mma_f16(acc[mt2][np2*2+1], afr[mt2], &bq[2]);
                }
            }
        }
        __syncthreads();
    }

    const int gr=lane>>2, gl=lane&3;
#pragma unroll
    for (int mt2=0; mt2<2; mt2++) {
#pragma unroll
        for (int nt2=0; nt2<8; nt2++) {
            int n = n0 + wn*64 + nt2*8 + gl*2;
            float b0=biasv[n], b1=biasv[n+1];
#pragma unroll
            for (int half_=0; half_<2; half_++) {
                int m = m0 + wm*32 + mt2*16 + gr + half_*8;
                float v0 = acc[mt2][nt2][half_*2+0] + b0;
                float v1 = acc[mt2][nt2][half_*2+1] + b1;
                if (MODE==0) {
                    *(float2*)&Cout[(size_t)m*Nn+n] = make_float2(v0,v1);
                } else {
                    int part=n/DIM, rem=n-part*DIM, h=rem>>6, d=rem&63;
                    int bb=m>>9, tok=m&511;
                    size_t o = ((size_t)((bb*NHEAD+h)*NTOK+tok))*HD + d;
                    if (part==0)      *(uint32_t*)(g_q+o) = pack_h2(v0*ATTN_SCALE, v1*ATTN_SCALE);
                    else if (part==1) *(uint32_t*)(g_k+o) = pack_h2(v0, v1);
                    else              *(uint32_t*)(g_v+o) = pack_h2(v0, v1);
                }
            }
        }
    }
}

// ---- FP16 mma flash attention (R10 version, unchanged) ----
__global__ __launch_bounds__(256,2)
void attn_mma_kernel()
{
    __shared__ uint32_t Qs[4096];
    __shared__ uint32_t KVs[2048];

    const int tid=threadIdx.x, warp=tid>>5, lane=tid&31, l_l=lane&3;
    const int row0=blockIdx.x*128, h=blockIdx.y, b=blockIdx.z;
    const size_t base = ((size_t)(b*NHEAD+h))*NTOK*HD;
    const int rt = blockIdx.x*8 + warp;

#pragma unroll
    for (int u=0; u<4; u++) {
        int f4=tid+256*u, row=f4>>3, ko=f4&7;
        uint4 q = *(const uint4*)(g_q + base + (size_t)(row0+row)*HD + ko*8);
        int ks=ko>>1, kh=ko&1, mt=row>>4, g=row&7, rh=(row>>3)&1;
        int sg=(ks^(g>>1))&3;
        int ab=(mt*4+ks)*128 + 16*g + rh + 2*kh;
        Qs[ab+4*(0^sg)]=q.x; Qs[ab+4*(1^sg)]=q.y;
        Qs[ab+4*(2^sg)]=q.z; Qs[ab+4*(3^sg)]=q.w;
    }

    float oacc[8][4];
#pragma unroll
    for(int i=0;i<8;i++)
#pragma unroll
        for(int j=0;j<4;j++) oacc[i][j]=0.f;
    float s0=0.f, s1=0.f;

    for (int ch=0; ch<8; ch++) {
        const int c0=ch*64;
        __syncthreads();

#pragma unroll
        for (int u=0; u<2; u++) {
            int f4=tid+256*u, key=f4>>3, ko=f4&7;
            uint4 kv = *(const uint4*)(g_k + base + (size_t)(c0+key)*HD + ko*8);
            int ks=ko>>1, kh=ko&1, nt=key>>3, g=key&7;
            int sg=(((ks^nt)&3)^(g>>1))&3;
            int bb=(nt*4+ks)*64 + 8*g + kh;
            KVs[bb+2*(0^sg)]=kv.x; KVs[bb+2*(1^sg)]=kv.y;
            KVs[bb+2*(2^sg)]=kv.z; KVs[bb+2*(3^sg)]=kv.w;
        }
        __syncthreads();

        float sf[8][4];
#pragma unroll
        for(int i=0;i<8;i++)
#pragma unroll
            for(int j=0;j<4;j++) sf[i][j]=0.f;
#pragma unroll
        for (int ks=0; ks<4; ks++) {
            int sa = lane ^ ((ks^(lane>>3))&3);
            uint32_t a[4];
            *(uint4*)a = *(const uint4*)&Qs[(warp*4+ks)*128 + 4*sa];
#pragma unroll
            for (int nt=0; nt<8; nt++) {
                int sb = lane ^ ((((ks^nt)&3)^(lane>>3))&3);
                uint32_t bb[2];
                *(uint2*)bb = *(const uint2*)&KVs[(nt*4+ks)*64 + 2*sb];
                mma_f16(sf[nt],a,bb);
            }
        }
        __syncthreads();

#pragma unroll
        for (int u=0; u<2; u++) {
            int f4=tid+256*u, key=f4>>3, d0=(f4&7)*8;
            uint4 vv = *(const uint4*)(g_v + base + (size_t)(c0+key)*HD + d0);
            const __half* vh = (const __half*)&vv;
            int nt=d0>>3, kcs=key>>4, reg=(key>>3)&1, l=(key>>1)&3, par=key&1;
            int wb = (nt*4+kcs)*64 + reg;
#pragma unroll
            for (int j=0; j<8; j++) {
                int sg=(((kcs^nt)&3)^(j>>1))&3;
                ((__half*)KVs)[(wb + 8*j + 2*(l^sg))*2 + par] = vh[j];
            }
        }

#pragma unroll
        for (int nt=0; nt<8; nt++) {
            float4 bf = *(const float4*)&g_biasp[
                ((((size_t)h*32+rt)*8+ch)*8+nt)*128 + lane*4];
            sf[nt][0]=__expf(sf[nt][0]+bf.x);
            sf[nt][1]=__expf(sf[nt][1]+bf.y);
            sf[nt][2]=__expf(sf[nt][2]+bf.z);
            sf[nt][3]=__expf(sf[nt][3]+bf.w);
            s0 += sf[nt][0]+sf[nt][1];
            s1 += sf[nt][2]+sf[nt][3];
        }
        __syncthreads();

#pragma unroll
        for (int kcs=0; kcs<4; kcs++) {
            uint32_t a[4];
            a[0] = pack_h2(sf[2*kcs  ][0], sf[2*kcs  ][1]);
            a[1] = pack_h2(sf[2*kcs  ][2], sf[2*kcs  ][3]);
            a[2] = pack_h2(sf[2*kcs+1][0], sf[2*kcs+1][1]);
            a[3] = pack_h2(sf[2*kcs+1][2], sf[2*kcs+1][3]);
#pragma unroll
            for (int nt=0; nt<8; nt++) {
                int sb = lane ^ ((((kcs^nt)&3)^(lane>>3))&3);
                uint32_t bb[2];
                *(uint2*)bb = *(const uint2*)&KVs[(nt*4+kcs)*64 + 2*sb];
                mma_f16(oacc[nt],a,bb);
            }
        }
    }

    s0 += __shfl_xor_sync(0xffffffffu,s0,1);
    s0 += __shfl_xor_sync(0xffffffffu,s0,2);
    s1 += __shfl_xor_sync(0xffffffffu,s1,1);
    s1 += __shfl_xor_sync(0xffffffffu,s1,2);
    float i0=1.f/s0, i1=1.f/s1;
    int rowA = row0 + warp*16 + (lane>>2);
#pragma unroll
    for (int nt=0; nt<8; nt++) {
        int col = h*HD + nt*8 + 2*l_l;
        *(uint32_t*)(g_attnout + ((size_t)b*NTOK+rowA)*DIM + col) =
            pack_h2(oacc[nt][0]*i0, oacc[nt][1]*i0);
        *(uint32_t*)(g_attnout + ((size_t)b*NTOK+rowA+8)*DIM + col) =
            pack_h2(oacc[nt][2]*i1, oacc[nt][3]*i1);
    }
}

extern "C" void kernel_launch(void* const* d_in, const int* in_sizes, int n_in,
                              void* d_out, int out_size)
{
    const float* x     = (const float*)d_in[0];
    const float* Wqkv  = (const float*)d_in[1];
    const float* bqkv  = (const float*)d_in[2];
    const float* table = (const float*)d_in[3];
    const int*   idx   = (const int*)  d_in[4];
    const float* Wproj = (const float*)d_in[5];
    const float* bproj = (const float*)d_in[6];
    float* out = (float*)d_out;

    __half* xr; __half* wqkvr; __half* wprojr;
    cudaGetSymbolAddress((void**)&xr,     g_xr);
    cudaGetSymbolAddress((void**)&wqkvr,  g_wr_qkv);
    cudaGetSymbolAddress((void**)&wprojr, g_wr_proj);

    half_copy_kernel<<<(MTOK*DIM/4 + 255)/256, 256>>>(x, xr, MTOK*DIM/4);
    half_copy_kernel<<<(QKV_N*DIM/4 + 255)/256, 256>>>(Wqkv, wqkvr, QKV_N*DIM/4);
    half_copy_kernel<<<(DIM*DIM/4 + 255)/256, 256>>>(Wproj, wprojr, DIM*DIM/4);

    bias_gather_kernel<<<(NTOK*NTOK)/256, 256>>>(table, idx);

    gemm_f16_kernel<1><<<dim3(QKV_N/128, MTOK/128), 256>>>(bqkv, nullptr,
                                                           MTOK, QKV_N, DIM);

    attn_mma_kernel<<<dim3(NTOK/128, NHEAD, NBATCH), 256>>>();

    gemm_f16_kernel<0><<<dim3(DIM/128, MTOK/128), 256>>>(bproj, out,
                                                         MTOK, DIM, DIM);
}

// round 15
// speedup vs baseline: 2.3801x; 1.0109x over previous
#include <cuda_runtime.h>
#include <cuda_fp16.h>
#include <cstdint>

#define NHEAD 12
#define HD 64
#define NTOK 512
#define NBATCH 32
#define DIM 768
#define MTOK (NBATCH*NTOK)
#define QKV_N (3*DIM)
#define ATTN_SCALE 0.125f

__device__ __half g_q[(size_t)NBATCH*NHEAD*NTOK*HD];
__device__ __half g_k[(size_t)NBATCH*NHEAD*NTOK*HD];
__device__ __half g_v[(size_t)NBATCH*NHEAD*NTOK*HD];
__device__ float  g_biasp[(size_t)NHEAD*NTOK*NTOK];  // c-frag layout
__device__ __half g_attnout[(size_t)MTOK*DIM];
__device__ __half g_xr[(size_t)MTOK*DIM];
__device__ __half g_wr_qkv[(size_t)QKV_N*DIM];
__device__ __half g_wr_proj[(size_t)DIM*DIM];

__device__ __forceinline__ uint32_t pack_h2(float lo, float hi){
    __half2 h = __floats2half2_rn(lo, hi);
    return *(uint32_t*)&h;
}
__device__ __forceinline__ void mma_f16(float* c, const uint32_t* a, const uint32_t* b){
    asm volatile("mma.sync.aligned.m16n8k16.row.col.f32.f16.f16.f32 "
        "{%0,%1,%2,%3}, {%4,%5,%6,%7}, {%8,%9}, {%0,%1,%2,%3};"
        : "+f"(c[0]),"+f"(c[1]),"+f"(c[2]),"+f"(c[3])
        : "r"(a[0]),"r"(a[1]),"r"(a[2]),"r"(a[3]),"r"(b[0]),"r"(b[1]));
}
__device__ __forceinline__ uint32_t smem_addr_of(const void* p){
    return (uint32_t)__cvta_generic_to_shared(p);
}
__device__ __forceinline__ void cp_async16(uint32_t dst, const void* src){
    asm volatile("cp.async.cg.shared.global [%0], [%1], 16;" :: "r"(dst), "l"(src));
}
__device__ __forceinline__ void cp_commit(){
    asm volatile("cp.async.commit_group;");
}
template<int N> __device__ __forceinline__ void cp_wait(){
    asm volatile("cp.async.wait_group %0;" :: "n"(N));
}
__device__ __forceinline__ void ldsm_x4(uint32_t* r, uint32_t addr){
    asm volatile("ldmatrix.sync.aligned.m8n8.x4.shared.b16 {%0,%1,%2,%3}, [%4];"
        : "=r"(r[0]),"=r"(r[1]),"=r"(r[2]),"=r"(r[3]) : "r"(addr));
}

// ---- float -> half copy ----
__global__ void half_copy_kernel(const float* __restrict__ src,
                                 __half* __restrict__ dst, int n4)
{
    int i = blockIdx.x*256 + threadIdx.x;
    if (i < n4) {
        float4 v = *(const float4*)&src[i*4];
        uint2 o;
        o.x = pack_h2(v.x, v.y);
        o.y = pack_h2(v.z, v.w);
        *(uint2*)(dst + (size_t)i*4) = o;
    }
}

// ---- bias gather into c-fragment layout ----
__global__ void bias_gather_kernel(const float* __restrict__ table,
                                   const int* __restrict__ idx)
{
    int e = blockIdx.x*256 + threadIdx.x;
    int rt=e>>13, kt=(e>>10)&7, nt=(e>>7)&7, lane=(e>>2)&31, reg=e&3;
    int g=lane>>2, l=lane&3;
    int row = rt*16 + g + 8*(reg>>1);
    int col = kt*64 + nt*8 + 2*l + (reg&1);
    int id = idx[row*NTOK + col];
    const float* t = table + (size_t)id*NHEAD;
#pragma unroll
    for (int h=0; h<NHEAD; h++)
        g_biasp[(size_t)h*262144 + e] = t[h];
}

// ---- FP16 GEMM: 3-stage cp.async pipeline + ldmatrix, 1 barrier/tile ----
// Smem tile: 128 rows x 128 B; byte = row*128 + ((c ^ (row&7))<<4).
template<int MODE>
__global__ __launch_bounds__(256,2)
void gemm_f16_kernel(const float* __restrict__ biasv, float* __restrict__ Cout,
                     int M, int Nn, int K)
{
    __shared__ __align__(128) __half As[3][128*64];   // 48 KB
    __shared__ __align__(128) __half Bs[3][128*64];   // 48 KB
    const __half* A  = (MODE==0) ? g_attnout : g_xr;
    const __half* Bw = (MODE==0) ? g_wr_proj : g_wr_qkv;
    const int tid=threadIdx.x, warp=tid>>5, lane=tid&31;
    const int wm=warp&3, wn=warp>>2;
    const int m0=blockIdx.y*128, n0=blockIdx.x*128;
    const int nT = K >> 6;

    const uint32_t aBase = smem_addr_of(As);
    const uint32_t bBase = smem_addr_of(Bs);

    // fill assignment: 4 chunks of A + 4 of B per thread per tile
    int frow[4]; uint32_t fdst[4]; int fc[4];
#pragma unroll
    for (int u=0; u<4; u++) {
        int f = tid + 256*u;            // 0..1023
        int row = f>>3, c = f&7;
        frow[u] = row; fc[u] = c;
        fdst[u] = (uint32_t)(row*128 + ((c ^ (row&7))<<4));
    }

    // ldmatrix per-thread invariants
    const int qa = lane>>3, ra = lane&7;
    int mrow[2];
#pragma unroll
    for (int mt2=0; mt2<2; mt2++)
        mrow[mt2] = (wm*2+mt2)*16 + (qa&1)*8 + ra;
    const int akc = qa>>1;
    const int ntsel = (lane>>4)&1, bkc = (lane>>3)&1;
    int nrow[4];
#pragma unroll
    for (int np2=0; np2<4; np2++)
        nrow[np2] = (wn*8 + np2*2 + ntsel)*8 + ra;

    float acc[2][8][4];
#pragma unroll
    for(int i=0;i<2;i++)
#pragma unroll
        for(int j=0;j<8;j++)
#pragma unroll
            for(int r=0;r<4;r++) acc[i][j][r]=0.f;

    // prologue: fill stages 0, 1
#pragma unroll
    for (int s=0; s<2; s++) {
        int kt = s<<6;
#pragma unroll
        for (int u=0; u<4; u++) {
            cp_async16(aBase + s*16384 + fdst[u],
                       A  + (size_t)(m0+frow[u])*K + kt + fc[u]*8);
            cp_async16(bBase + s*16384 + fdst[u],
                       Bw + (size_t)(n0+frow[u])*K + kt + fc[u]*8);
        }
        cp_commit();
    }

    int cur = 0;
    for (int t=0; t<nT; t++) {
        cp_wait<1>();
        __syncthreads();

        const uint32_t aS = aBase + cur*16384;
        const uint32_t bS = bBase + cur*16384;
#pragma unroll
        for (int ks=0; ks<4; ks++) {
            uint32_t afr[2][4];
#pragma unroll
            for (int mt2=0; mt2<2; mt2++) {
                int m = mrow[mt2];
                int kc = ks*2 + akc;
                ldsm_x4(afr[mt2], aS + m*128 + ((kc ^ (m&7))<<4));
            }
#pragma unroll
            for (int np2=0; np2<4; np2++) {
                int n = nrow[np2];
                int kc = ks*2 + bkc;
                uint32_t bq[4];
                ldsm_x4(bq, bS + n*128 + ((kc ^ (n&7))<<4));
#pragma unroll
                for (int mt2=0; mt2<2; mt2++) {
                    mma_f16(acc[mt2][np2*2+0], afr[mt2], &bq[0]);
                    mma_f16(acc[mt2][np2*2+1], afr[mt2], &bq[2]);
                }
            }
        }

        if (t+2 < nT) {
            int s = cur+2; if (s>=3) s-=3;
            int kt = (t+2)<<6;
#pragma unroll
            for (int u=0; u<4; u++) {
                cp_async16(aBase + s*16384 + fdst[u],
                           A  + (size_t)(m0+frow[u])*K + kt + fc[u]*8);
                cp_async16(bBase + s*16384 + fdst[u],
                           Bw + (size_t)(n0+frow[u])*K + kt + fc[u]*8);
            }
        }
        cp_commit();   // empty group near the tail keeps wait<1> aligned
        if (++cur == 3) cur = 0;
    }

    const int gr=lane>>2, gl=lane&3;
#pragma unroll
    for (int mt2=0; mt2<2; mt2++) {
#pragma unroll
        for (int nt2=0; nt2<8; nt2++) {
            int n = n0 + wn*64 + nt2*8 + gl*2;
            float b0=biasv[n], b1=biasv[n+1];
#pragma unroll
            for (int half_=0; half_<2; half_++) {
                int m = m0 + wm*32 + mt2*16 + gr + half_*8;
                float v0 = acc[mt2][nt2][half_*2+0] + b0;
                float v1 = acc[mt2][nt2][half_*2+1] + b1;
                if (MODE==0) {
                    *(float2*)&Cout[(size_t)m*Nn+n] = make_float2(v0,v1);
                } else {
                    int part=n/DIM, rem=n-part*DIM, h=rem>>6, d=rem&63;
                    int bb=m>>9, tok=m&511;
                    size_t o = ((size_t)((bb*NHEAD+h)*NTOK+tok))*HD + d;
                    if (part==0)      *(uint32_t*)(g_q+o) = pack_h2(v0*ATTN_SCALE, v1*ATTN_SCALE);
                    else if (part==1) *(uint32_t*)(g_k+o) = pack_h2(v0, v1);
                    else              *(uint32_t*)(g_v+o) = pack_h2(v0, v1);
                }
            }
        }
    }
}

// ---- FP16 mma flash attention (R10/R11 version, unchanged) ----
__global__ __launch_bounds__(256,2)
void attn_mma_kernel()
{
    __shared__ uint32_t Qs[4096];
    __shared__ uint32_t KVs[2048];

    const int tid=threadIdx.x, warp=tid>>5, lane=tid&31, l_l=lane&3;
    const int row0=blockIdx.x*128, h=blockIdx.y, b=blockIdx.z;
    const size_t base = ((size_t)(b*NHEAD+h))*NTOK*HD;
    const int rt = blockIdx.x*8 + warp;

#pragma unroll
    for (int u=0; u<4; u++) {
        int f4=tid+256*u, row=f4>>3, ko=f4&7;
        uint4 q = *(const uint4*)(g_q + base + (size_t)(row0+row)*HD + ko*8);
        int ks=ko>>1, kh=ko&1, mt=row>>4, g=row&7, rh=(row>>3)&1;
        int sg=(ks^(g>>1))&3;
        int ab=(mt*4+ks)*128 + 16*g + rh + 2*kh;
        Qs[ab+4*(0^sg)]=q.x; Qs[ab+4*(1^sg)]=q.y;
        Qs[ab+4*(2^sg)]=q.z; Qs[ab+4*(3^sg)]=q.w;
    }

    float oacc[8][4];
#pragma unroll
    for(int i=0;i<8;i++)
#pragma unroll
        for(int j=0;j<4;j++) oacc[i][j]=0.f;
    float s0=0.f, s1=0.f;

    for (int ch=0; ch<8; ch++) {
        const int c0=ch*64;
        __syncthreads();

#pragma unroll
        for (int u=0; u<2; u++) {
            int f4=tid+256*u, key=f4>>3, ko=f4&7;
            uint4 kv = *(const uint4*)(g_k + base + (size_t)(c0+key)*HD + ko*8);
            int ks=ko>>1, kh=ko&1, nt=key>>3, g=key&7;
            int sg=(((ks^nt)&3)^(g>>1))&3;
            int bb=(nt*4+ks)*64 + 8*g + kh;
            KVs[bb+2*(0^sg)]=kv.x; KVs[bb+2*(1^sg)]=kv.y;
            KVs[bb+2*(2^sg)]=kv.z; KVs[bb+2*(3^sg)]=kv.w;
        }
        __syncthreads();

        float sf[8][4];
#pragma unroll
        for(int i=0;i<8;i++)
#pragma unroll
            for(int j=0;j<4;j++) sf[i][j]=0.f;
#pragma unroll
        for (int ks=0; ks<4; ks++) {
            int sa = lane ^ ((ks^(lane>>3))&3);
            uint32_t a[4];
            *(uint4*)a = *(const uint4*)&Qs[(warp*4+ks)*128 + 4*sa];
#pragma unroll
            for (int nt=0; nt<8; nt++) {
                int sb = lane ^ ((((ks^nt)&3)^(lane>>3))&3);
                uint32_t bb[2];
                *(uint2*)bb = *(const uint2*)&KVs[(nt*4+ks)*64 + 2*sb];
                mma_f16(sf[nt],a,bb);
            }
        }
        __syncthreads();

#pragma unroll
        for (int u=0; u<2; u++) {
            int f4=tid+256*u, key=f4>>3, d0=(f4&7)*8;
            uint4 vv = *(const uint4*)(g_v + base + (size_t)(c0+key)*HD + d0);
            const __half* vh = (const __half*)&vv;
            int nt=d0>>3, kcs=key>>4, reg=(key>>3)&1, l=(key>>1)&3, par=key&1;
            int wb = (nt*4+kcs)*64 + reg;
#pragma unroll
            for (int j=0; j<8; j++) {
                int sg=(((kcs^nt)&3)^(j>>1))&3;
                ((__half*)KVs)[(wb + 8*j + 2*(l^sg))*2 + par] = vh[j];
            }
        }

#pragma unroll
        for (int nt=0; nt<8; nt++) {
            float4 bf = *(const float4*)&g_biasp[
                ((((size_t)h*32+rt)*8+ch)*8+nt)*128 + lane*4];
            sf[nt][0]=__expf(sf[nt][0]+bf.x);
            sf[nt][1]=__expf(sf[nt][1]+bf.y);
            sf[nt][2]=__expf(sf[nt][2]+bf.z);
            sf[nt][3]=__expf(sf[nt][3]+bf.w);
            s0 += sf[nt][0]+sf[nt][1];
            s1 += sf[nt][2]+sf[nt][3];
        }
        __syncthreads();

#pragma unroll
        for (int kcs=0; kcs<4; kcs++) {
            uint32_t a[4];
            a[0] = pack_h2(sf[2*kcs  ][0], sf[2*kcs  ][1]);
            a[1] = pack_h2(sf[2*kcs  ][2], sf[2*kcs  ][3]);
            a[2] = pack_h2(sf[2*kcs+1][0], sf[2*kcs+1][1]);
            a[3] = pack_h2(sf[2*kcs+1][2], sf[2*kcs+1][3]);
#pragma unroll
            for (int nt=0; nt<8; nt++) {
                int sb = lane ^ ((((kcs^nt)&3)^(lane>>3))&3);
                uint32_t bb[2];
                *(uint2*)bb = *(const uint2*)&KVs[(nt*4+kcs)*64 + 2*sb];
                mma_f16(oacc[nt],a,bb);
            }
        }
    }

    s0 += __shfl_xor_sync(0xffffffffu,s0,1);
    s0 += __shfl_xor_sync(0xffffffffu,s0,2);
    s1 += __shfl_xor_sync(0xffffffffu,s1,1);
    s1 += __shfl_xor_sync(0xffffffffu,s1,2);
    float i0=1.f/s0, i1=1.f/s1;
    int rowA = row0 + warp*16 + (lane>>2);
#pragma unroll
    for (int nt=0; nt<8; nt++) {
        int col = h*HD + nt*8 + 2*l_l;
        *(uint32_t*)(g_attnout + ((size_t)b*NTOK+rowA)*DIM + col) =
            pack_h2(oacc[nt][0]*i0, oacc[nt][1]*i0);
        *(uint32_t*)(g_attnout + ((size_t)b*NTOK+rowA+8)*DIM + col) =
            pack_h2(oacc[nt][2]*i1, oacc[nt][3]*i1);
    }
}

extern "C" void kernel_launch(void* const* d_in, const int* in_sizes, int n_in,
                              void* d_out, int out_size)
{
    const float* x     = (const float*)d_in[0];
    const float* Wqkv  = (const float*)d_in[1];
    const float* bqkv  = (const float*)d_in[2];
    const float* table = (const float*)d_in[3];
    const int*   idx   = (const int*)  d_in[4];
    const float* Wproj = (const float*)d_in[5];
    const float* bproj = (const float*)d_in[6];
    float* out = (float*)d_out;

    __half* xr; __half* wqkvr; __half* wprojr;
    cudaGetSymbolAddress((void**)&xr,     g_xr);
    cudaGetSymbolAddress((void**)&wqkvr,  g_wr_qkv);
    cudaGetSymbolAddress((void**)&wprojr, g_wr_proj);

    half_copy_kernel<<<(MTOK*DIM/4 + 255)/256, 256>>>(x, xr, MTOK*DIM/4);
    half_copy_kernel<<<(QKV_N*DIM/4 + 255)/256, 256>>>(Wqkv, wqkvr, QKV_N*DIM/4);
    half_copy_kernel<<<(DIM*DIM/4 + 255)/256, 256>>>(Wproj, wprojr, DIM*DIM/4);

    bias_gather_kernel<<<(NTOK*NTOK)/256, 256>>>(table, idx);

    gemm_f16_kernel<1><<<dim3(QKV_N/128, MTOK/128), 256>>>(bqkv, nullptr,
                                                           MTOK, QKV_N, DIM);

    attn_mma_kernel<<<dim3(NTOK/128, NHEAD, NBATCH), 256>>>();

    gemm_f16_kernel<0><<<dim3(DIM/128, MTOK/128), 256>>>(bproj, out,
                                                         MTOK, DIM, DIM);
}